// round 8
// baseline (speedup 1.0000x reference)
#include <cuda_runtime.h>
#include <cuda_bf16.h>
#include <cstdint>

// out[r][c] = in[2r+1][2c+1], in: 8192x8192 fp32, out: 4096x4096 fp32.
// Reads: R2's proven path — front-batched __ldcs LDG.128, MLP=8/thread.
// Writes: staged in smem, then ONE 16KB cp.async.bulk (TMA) store per CTA:
// perfectly sequential DRAM write bursts, store traffic off the L1/LSU path.

#define N_IN   8192
#define N_OUT  4096
#define F4_ROW (N_OUT / 4)   // 1024 output float4s per row = 16KB
#define TPB    256
#define UNROLL 4             // F4_ROW / TPB

__global__ __launch_bounds__(TPB) void decimate2_kernel(
    const float4* __restrict__ in, float4* __restrict__ out)
{
    __shared__ __align__(128) float4 buf[F4_ROW];   // 16KB staging

    const int orow = blockIdx.x;
    const int tid  = threadIdx.x;

    const float4* in_row = in + (size_t)(2 * orow + 1) * (N_IN / 4);

    float4 a[UNROLL], b[UNROLL];

    // Front-batched loads: 8 independent LDG.128 in flight per thread.
#pragma unroll
    for (int k = 0; k < UNROLL; k++) {
        const int oc4 = tid + k * TPB;
        a[k] = __ldcs(&in_row[2 * oc4]);
        b[k] = __ldcs(&in_row[2 * oc4 + 1]);
    }

    // Stage into smem (STS.128, consecutive lanes -> conflict-free).
#pragma unroll
    for (int k = 0; k < UNROLL; k++) {
        const int oc4 = tid + k * TPB;
        float4 r;
        r.x = a[k].y;   // odd col 8*oc4+1
        r.y = a[k].w;   // odd col 8*oc4+3
        r.z = b[k].y;   // odd col 8*oc4+5
        r.w = b[k].w;   // odd col 8*oc4+7
        buf[oc4] = r;
    }

    __syncthreads();

    // One thread issues a single 16KB bulk store: smem -> gmem.
    if (tid == 0) {
        // Order generic-proxy smem writes before async-proxy read.
        asm volatile("fence.proxy.async.shared::cta;" ::: "memory");

        uint32_t s_addr;
        asm("{ .reg .u64 t; cvta.to.shared.u64 t, %1; cvt.u32.u64 %0, t; }"
            : "=r"(s_addr) : "l"(buf));

        float4* dst = out + (size_t)orow * F4_ROW;
        asm volatile(
            "cp.async.bulk.global.shared::cta.bulk_group [%0], [%1], %2;"
            :: "l"(dst), "r"(s_addr), "r"((int)(F4_ROW * sizeof(float4)))
            : "memory");
        asm volatile("cp.async.bulk.commit_group;" ::: "memory");
        asm volatile("cp.async.bulk.wait_group 0;" ::: "memory");
    }
}

extern "C" void kernel_launch(void* const* d_in, const int* in_sizes, int n_in,
                              void* d_out, int out_size)
{
    const float4* in  = (const float4*)d_in[0];
    float4*       out = (float4*)d_out;

    decimate2_kernel<<<N_OUT, TPB>>>(in, out);
}

// round 9
// speedup vs baseline: 1.0374x; 1.0374x over previous
#include <cuda_runtime.h>
#include <cuda_bf16.h>
#include <cstdint>

// out[r][c] = in[2r+1][2c+1], in: 8192x8192 fp32, out: 4096x4096 fp32.
// Persistent version of R2 (best kernel): exactly one wave of CTAs
// (148 SMs x 8 CTAs = 1184), each grid-striding over output rows.
// Inner body identical to R2: 8 front-batched __ldcs LDG.128 per thread,
// then 4 contiguous STG.128. Removes 2.5 waves of wave-transition +
// ragged-tail overhead.

#define N_IN    8192
#define N_OUT   4096
#define F4_ROW  (N_OUT / 4)   // 1024 output float4s per row
#define TPB     256
#define UNROLL  4             // F4_ROW / TPB
#define GRID    1184          // 148 SMs * 8 CTAs (occ limit at 256 thr, 26 regs)

__global__ __launch_bounds__(TPB) void decimate2_kernel(
    const float4* __restrict__ in, float4* __restrict__ out)
{
    const int tid = threadIdx.x;

    for (int orow = blockIdx.x; orow < N_OUT; orow += GRID) {
        const float4* in_row  = in  + (size_t)(2 * orow + 1) * (N_IN / 4);
        float4*       out_row = out + (size_t)orow * F4_ROW;

        float4 a[UNROLL], b[UNROLL];

        // Front-batched loads: 8 independent LDG.128 in flight per thread.
#pragma unroll
        for (int k = 0; k < UNROLL; k++) {
            const int oc4 = tid + k * TPB;
            a[k] = __ldcs(&in_row[2 * oc4]);
            b[k] = __ldcs(&in_row[2 * oc4 + 1]);
        }

#pragma unroll
        for (int k = 0; k < UNROLL; k++) {
            const int oc4 = tid + k * TPB;
            float4 r;
            r.x = a[k].y;   // odd col 8*oc4+1
            r.y = a[k].w;   // odd col 8*oc4+3
            r.z = b[k].y;   // odd col 8*oc4+5
            r.w = b[k].w;   // odd col 8*oc4+7
            out_row[oc4] = r;
        }
    }
}

extern "C" void kernel_launch(void* const* d_in, const int* in_sizes, int n_in,
                              void* d_out, int out_size)
{
    const float4* in  = (const float4*)d_in[0];
    float4*       out = (float4*)d_out;

    decimate2_kernel<<<GRID, TPB>>>(in, out);
}